// round 16
// baseline (speedup 1.0000x reference)
#include <cuda_runtime.h>
#include <cuda_fp16.h>
#include <math.h>
#include <stdint.h>

// Problem constants
#define B_  256
#define T_  200
#define E_  584
#define H_  8
#define HS_ 73
#define HSP 74           // padded head stride (halves)
#define XP  592          // padded fp16 row stride for x / weights (16B multiple)
#define BH_ (B_*H_)      // 2048
#define M_  (B_*T_)      // 51200

// Scratch (allocation-free rule: __device__ globals; zero-init at load)
__device__ __half g_q[BH_*T_*HSP + 32];
__device__ __half g_k[BH_*T_*HSP + 32];
__device__ __half g_v[BH_*T_*HSP + 32];
__device__ __half g_atth[M_*E_ + 32];
__device__ __half g_xh[(size_t)M_*XP];
__device__ __half g_wh[1752*XP];      // Wq|Wk|Wv rows stacked
__device__ __half g_woh[E_*XP];

__device__ __forceinline__ uint32_t f2h2(float lo, float hi) {
    __half2 h = __floats2half2_rn(lo, hi);
    return *reinterpret_cast<uint32_t*>(&h);
}

__device__ __forceinline__ void mma_f16(float c[4],
                                        uint32_t a0, uint32_t a1, uint32_t a2, uint32_t a3,
                                        uint32_t b0, uint32_t b1) {
    asm volatile(
        "mma.sync.aligned.m16n8k16.row.col.f32.f16.f16.f32 "
        "{%0,%1,%2,%3}, {%4,%5,%6,%7}, {%8,%9}, {%0,%1,%2,%3};"
        : "+f"(c[0]), "+f"(c[1]), "+f"(c[2]), "+f"(c[3])
        : "r"(a0), "r"(a1), "r"(a2), "r"(a3), "r"(b0), "r"(b1));
}

__device__ __forceinline__ void ldm_x4(uint32_t& r0, uint32_t& r1,
                                       uint32_t& r2, uint32_t& r3, uint32_t a) {
    asm volatile("ldmatrix.sync.aligned.m8n8.x4.shared.b16 {%0,%1,%2,%3}, [%4];"
                 : "=r"(r0), "=r"(r1), "=r"(r2), "=r"(r3) : "r"(a));
}

__device__ __forceinline__ uint32_t s2u(const void* p) {
    return (uint32_t)__cvta_generic_to_shared(p);
}
__device__ __forceinline__ void cp16(uint32_t d, const void* s, bool v) {
    asm volatile("cp.async.ca.shared.global [%0], [%1], 16, %2;"
                 :: "r"(d), "l"(s), "r"(v ? 16 : 0));
}
__device__ __forceinline__ void cp_commit() { asm volatile("cp.async.commit_group;"); }
__device__ __forceinline__ void cp_wait2()  { asm volatile("cp.async.wait_group 2;"); }
__device__ __forceinline__ void named_bar(int id, int cnt) {
    asm volatile("bar.sync %0, %1;" :: "r"(id), "r"(cnt) : "memory");
}

// ---------------------------------------------------------------------------
// Conversion prep kernels (fp32 -> padded fp16)
// ---------------------------------------------------------------------------
__global__ void cvt_x(const float* __restrict__ x) {
    const int W = XP / 2;
    int i = blockIdx.x * 256 + threadIdx.x;
    if (i >= M_ * W) return;
    int m = i / W, c2 = (i - m * W) * 2;
    float lo = (c2     < E_) ? x[(size_t)m * E_ + c2]     : 0.f;
    float hi = (c2 + 1 < E_) ? x[(size_t)m * E_ + c2 + 1] : 0.f;
    reinterpret_cast<uint32_t*>(g_xh)[i] = f2h2(lo, hi);
}

__global__ void cvt_w(const float* __restrict__ Wq, const float* __restrict__ Wk,
                      const float* __restrict__ Wv, const float* __restrict__ Wo) {
    const int W = XP / 2;
    int i = blockIdx.x * 256 + threadIdx.x;
    if (i >= (1752 + E_) * W) return;
    int row = i / W, c2 = (i - row * W) * 2;
    const float* src;
    uint32_t* dst;
    int r;
    if (row < 1752) {
        int s = row / E_;
        r = row - s * E_;
        src = (s == 0) ? Wq : ((s == 1) ? Wk : Wv);
        dst = reinterpret_cast<uint32_t*>(g_wh) + (size_t)row * W;
    } else {
        r = row - 1752;
        src = Wo;
        dst = reinterpret_cast<uint32_t*>(g_woh) + (size_t)r * W;
    }
    float lo = (c2     < E_) ? src[(size_t)r * E_ + c2]     : 0.f;
    float hi = (c2 + 1 < E_) ? src[(size_t)r * E_ + c2 + 1] : 0.f;
    dst[i - row * W] = f2h2(lo, hi);
}

// ---------------------------------------------------------------------------
// FP16 GEMM v2: 512 threads (16 warps, 4m x 4n), warp tile 32x32, CTA 128x128,
// BK=32, cp.async 4-stage. 2 CTAs/SM -> 32 warps/SM.
// MODE 0: qkv (A=g_xh/XP, B=g_wh/XP; fp16 scatter, q scaled)
// MODE 1: out (A=g_atth/E_, B=g_woh/XP; +bias -> f32 out)
// ---------------------------------------------------------------------------
#define ROWPW  20
#define BK     32
#define STAGES 4
#define NSTG   19
#define TWW    (128*ROWPW)
#define GSMEM  (STAGES*2*TWW*4)

template<int MODE>
__global__ __launch_bounds__(512, 2)
void gemm_f16(const float* __restrict__ bias, float* __restrict__ out)
{
    extern __shared__ uint32_t gsm[];
    uint32_t* As = gsm;               // [STAGES][TWW]
    uint32_t* Bs = gsm + STAGES*TWW;  // [STAGES][TWW]

    const __half* A = (MODE == 0) ? g_xh  : g_atth;
    const __half* Bm = (MODE == 0) ? g_wh : g_woh;
    const int strideA = (MODE == 0) ? XP : E_;
    const int availA  = (MODE == 0) ? XP : E_;
    const int Ntot    = (MODE == 0) ? 1752 : E_;

    const int tid  = threadIdx.x;
    const int lane = tid & 31;
    const int w    = tid >> 5;       // 0..15
    const int g    = lane >> 2;
    const int c    = lane & 3;
    const int wm   = w & 3;          // 4 m-warps, 32 rows each
    const int wn   = w >> 2;         // 4 n-warps, 32 cols each

    const int m0 = blockIdx.y * 128;
    const int n0 = blockIdx.x * 128;

    float acc[2][4][4];
#pragma unroll
    for (int mi = 0; mi < 2; mi++)
#pragma unroll
        for (int ni = 0; ni < 4; ni++)
#pragma unroll
            for (int r = 0; r < 4; r++) acc[mi][ni][r] = 0.f;

    // staging: thread owns row tid>>2, chunk (tid&3) of 8 halves (16B)
    const int row = tid >> 2;
    const int kc  = tid & 3;

    const __half* aptr = A + (size_t)(m0 + row) * strideA + kc * 8;
    const int gn = n0 + row;
    const bool bval = gn < Ntot;
    const __half* bptr = Bm + (size_t)(bval ? gn : 0) * XP + kc * 8;

    const uint32_t a_s0 = s2u(&As[row * ROWPW + kc * 4]);
    const uint32_t b_s0 = s2u(&Bs[row * ROWPW + kc * 4]);
    const uint32_t stage_bytes = TWW * 4;

    auto issue = [&](int s) {
        if (s < NSTG) {
            const int kb = s * BK;
            const int slot = s % STAGES;
            const int kk = kb + kc * 8;
            cp16(a_s0 + slot * stage_bytes, aptr + kb, kk + 8 <= availA);
            cp16(b_s0 + slot * stage_bytes, bptr + kb, bval && (kk + 8 <= XP));
        }
        cp_commit();
    };

    const int lr = lane & 15, lh = lane >> 4;
    uint32_t aAdr[2], bAdr[2];
#pragma unroll
    for (int mi = 0; mi < 2; mi++)
        aAdr[mi] = s2u(&As[0]) + (uint32_t)(((wm*32 + mi*16 + lr) * ROWPW + lh*4) * 4);
#pragma unroll
    for (int np = 0; np < 2; np++)
        bAdr[np] = s2u(&Bs[0]) + (uint32_t)(((wn*32 + np*16 + lr) * ROWPW + lh*4) * 4);

    issue(0);
    issue(1);
    issue(2);

#pragma unroll 1
    for (int s = 0; s < NSTG; s++) {
        cp_wait2();
        __syncthreads();
        issue(s + 3);

        const uint32_t kb = (uint32_t)(s % STAGES) * stage_bytes;
#pragma unroll
        for (int t16 = 0; t16 < 2; t16++) {
            const uint32_t ko = kb + t16 * 32;   // 16 halves = 32 bytes
            uint32_t a[2][4], bm[2][4];
#pragma unroll
            for (int mi = 0; mi < 2; mi++)
                ldm_x4(a[mi][0], a[mi][1], a[mi][2], a[mi][3], aAdr[mi] + ko);
#pragma unroll
            for (int np = 0; np < 2; np++)
                ldm_x4(bm[np][0], bm[np][1], bm[np][2], bm[np][3], bAdr[np] + ko);
#pragma unroll
            for (int mi = 0; mi < 2; mi++)
#pragma unroll
                for (int np = 0; np < 2; np++) {
                    mma_f16(acc[mi][2*np],   a[mi][0], a[mi][1], a[mi][2], a[mi][3],
                            bm[np][0], bm[np][2]);
                    mma_f16(acc[mi][2*np+1], a[mi][0], a[mi][1], a[mi][2], a[mi][3],
                            bm[np][1], bm[np][3]);
                }
        }
    }

    const float scale = rsqrtf((float)E_);
#pragma unroll
    for (int mi = 0; mi < 2; mi++) {
#pragma unroll
        for (int ni = 0; ni < 4; ni++) {
#pragma unroll
            for (int r = 0; r < 4; r++) {
                const int m = m0 + wm * 32 + mi * 16 + g + ((r >= 2) ? 8 : 0);
                const int n = n0 + wn * 32 + ni * 8 + 2 * c + (r & 1);
                const float v = acc[mi][ni][r];
                if (MODE == 0) {
                    if (n < 3 * E_) {
                        const int sidx = n / E_;
                        const int l    = n - sidx * E_;
                        const int hh   = l / HS_;
                        const int f    = l - hh * HS_;
                        const int bb   = m / T_;
                        const int t    = m - bb * T_;
                        __half* dst = (sidx == 0) ? g_q : ((sidx == 1) ? g_k : g_v);
                        const float vv = (sidx == 0) ? v * scale : v;
                        dst[((size_t)(bb * H_ + hh) * T_ + t) * HSP + f] = __float2half(vv);
                    }
                } else {
                    if (n < E_)
                        out[(size_t)m * E_ + n] = v + bias[n];
                }
            }
        }
    }
}

// ---------------------------------------------------------------------------
// FP16 attention v5b (R15, unchanged — passing @ 4.75e-4, 318us)
// ---------------------------------------------------------------------------
#define KSW 44
#define VTW 108
#define PTW 108
#define ATT_WORDS (208*KSW + 80*VTW + 64*PTW + 512)

__global__ __launch_bounds__(512, 2)
void attn_mma()
{
    extern __shared__ uint32_t smu[];
    uint32_t* Ks = smu;                    // [208][44]
    uint32_t* Vt = Ks + 208*KSW;           // [80][108]
    uint32_t* Pt = Vt + 80*VTW;            // [64][108]
    float* psum  = (float*)(Pt + 64*PTW);  // [64][4]

    const int bh   = blockIdx.x;
    const int tid  = threadIdx.x;
    const int lane = tid & 31;
    const int w    = tid >> 5;
    const int g    = lane >> 2;
    const int c    = lane & 3;
    const int wm   = w & 3;
    const int wn   = w >> 2;
    const int b    = bh / H_;
    const int h    = bh - b * H_;
    const int barid = 1 + wm;

    const __half* qg = g_q + (size_t)bh * T_ * HSP;
    const __half* kg = g_k + (size_t)bh * T_ * HSP;
    const __half* vg = g_v + (size_t)bh * T_ * HSP;

    for (int i = tid; i < 208*40; i += 512) {
        const int s = i / 40, f2 = i - s * 40;
        uint32_t val = 0;
        if (s < T_) {
            if (2*f2 + 1 < HS_) val = *(const uint32_t*)(kg + (size_t)s*HSP + 2*f2);
            else if (2*f2 < HS_) val = (uint32_t)__half_as_ushort(kg[(size_t)s*HSP + 2*f2]);
        }
        Ks[s*KSW + f2] = val;
    }
    for (int i = tid; i < 80*104; i += 512) {
        const int f = i / 104, s2 = i - f * 104;
        __half lo = (2*s2   < T_ && f < HS_) ? vg[(size_t)(2*s2  )*HSP + f] : __ushort_as_half((unsigned short)0);
        __half hi = (2*s2+1 < T_ && f < HS_) ? vg[(size_t)(2*s2+1)*HSP + f] : __ushort_as_half((unsigned short)0);
        __half2 p = __halves2half2(lo, hi);
        Vt[f*VTW + s2] = *reinterpret_cast<uint32_t*>(&p);
    }
    __syncthreads();

    const int mr = wm * 16;
    const int rq_lo = mr + g;
    const int rq_hi = mr + g + 8;

    const int lr = lane & 15, lh = lane >> 4;
    const uint32_t kBase = s2u(Ks) + (uint32_t)((lr * KSW + lh * 4) * 4);
    const uint32_t pBase = s2u(Pt) + (uint32_t)(((mr + lr) * PTW + lh * 4) * 4);

#pragma unroll 1
    for (int t0 = 0; t0 < T_; t0 += 64) {
        const int thi = t0 + mr + 15;

        const int row_lo = (t0 + rq_lo < T_) ? (t0 + rq_lo) : (T_ - 1);
        const int row_hi = (t0 + rq_hi < T_) ? (t0 + rq_hi) : (T_ - 1);
        const __half* qlo = qg + (size_t)row_lo * HSP;
        const __half* qhi = qg + (size_t)row_hi * HSP;

        float acc[4][2][4];
#pragma unroll
        for (int u = 0; u < 4; u++)
#pragma unroll
            for (int e = 0; e < 2; e++)
#pragma unroll
                for (int r = 0; r < 4; r++) acc[u][e][r] = 0.f;

        // ---- S = Q.K^T ------------------------------------------------------
#pragma unroll
        for (int ks = 0; ks < 80; ks += 16) {
            const int k0 = ks + 2*c;
            const int k1 = k0 + 8;
            const uint32_t a0 = *(const uint32_t*)(qlo + k0);
            const uint32_t a1 = *(const uint32_t*)(qhi + k0);
            const uint32_t a2 = *(const uint32_t*)(qlo + k1);
            const uint32_t a3 = *(const uint32_t*)(qhi + k1);
#pragma unroll
            for (int u = 0; u < 4; u++) {
                const int chunk = 4*u + wn;
                const int cb = chunk * 16;
                if (chunk < 13 && cb <= thi) {
                    uint32_t b0, b1, b2, b3;
                    ldm_x4(b0, b1, b2, b3, kBase + (uint32_t)(cb * (KSW*4) + ks * 2));
                    mma_f16(acc[u][0], a0, a1, a2, a3, b0, b2);
                    mma_f16(acc[u][1], a0, a1, a2, a3, b1, b3);
                }
            }
        }

        // ---- single-pass softmax: exp, sum, store unnormalized P (guarded) --
        const int t_lo = t0 + rq_lo;
        const int t_hi = t0 + rq_hi;

        float slo = 0.f, shi = 0.f;
#pragma unroll
        for (int u = 0; u < 4; u++) {
            const int chunk = 4*u + wn;
#pragma unroll
            for (int e = 0; e < 2; e++) {
                const int s0 = chunk*16 + e*8 + 2*c;
                const int s1 = s0 + 1;
                const bool ok0l = (s0 <= t_lo) && (s0 < T_) && (t_lo < T_);
                const bool ok1l = (s1 <= t_lo) && (s1 < T_) && (t_lo < T_);
                const bool ok0h = (s0 <= t_hi) && (s0 < T_) && (t_hi < T_);
                const bool ok1h = (s1 <= t_hi) && (s1 < T_) && (t_hi < T_);
                float e0 = ok0l ? __expf(acc[u][e][0]) : 0.f;
                float e1 = ok1l ? __expf(acc[u][e][1]) : 0.f;
                float e2 = ok0h ? __expf(acc[u][e][2]) : 0.f;
                float e3 = ok1h ? __expf(acc[u][e][3]) : 0.f;
                slo += e0 + e1;  shi += e2 + e3;
                if (chunk < 13) {
                    const int cw = chunk*8 + e*4 + c;
                    Pt[rq_lo*PTW + cw] = f2h2(e0, e1);
                    Pt[rq_hi*PTW + cw] = f2h2(e2, e3);
                }
            }
        }
#pragma unroll
        for (int off = 1; off <= 2; off <<= 1) {
            slo += __shfl_xor_sync(0xffffffffu, slo, off);
            shi += __shfl_xor_sync(0xffffffffu, shi, off);
        }
        if (c == 0) {
            psum[rq_lo*4 + wn] = slo;
            psum[rq_hi*4 + wn] = shi;
        }
        named_bar(barid, 128);
        const float tlo  = psum[rq_lo*4] + psum[rq_lo*4+1] + psum[rq_lo*4+2] + psum[rq_lo*4+3];
        const float thi2 = psum[rq_hi*4] + psum[rq_hi*4+1] + psum[rq_hi*4+2] + psum[rq_hi*4+3];
        const float rlo = (tlo  > 0.f) ? (1.f / tlo)  : 0.f;
        const float rhi = (thi2 > 0.f) ? (1.f / thi2) : 0.f;

        // ---- O = P.V (unnormalized P; scale at epilogue) ---------------------
        float o[3][4];
#pragma unroll
        for (int j = 0; j < 3; j++)
#pragma unroll
            for (int r = 0; r < 4; r++) o[j][r] = 0.f;

        const int kcap    = (thi < T_-1) ? thi : (T_-1);
        const int ksb_end = kcap >> 4;
#pragma unroll 1
        for (int ksb = 0; ksb <= ksb_end; ksb++) {
            uint32_t a0, a1, a2, a3;
            ldm_x4(a0, a1, a2, a3, pBase + (uint32_t)(ksb * 32));
#pragma unroll
            for (int j = 0; j < 3; j++) {
                const int nt = wn + 4*j;
                if (nt < 10) {
                    const uint32_t b0 = Vt[(nt*8 + g)*VTW + ksb*8 + c];
                    const uint32_t b1 = Vt[(nt*8 + g)*VTW + ksb*8 + c + 4];
                    mma_f16(o[j], a0, a1, a2, a3, b0, b1);
                }
            }
        }

#pragma unroll
        for (int j = 0; j < 3; j++) {
            const int nt = wn + 4*j;
            if (nt < 10) {
#pragma unroll
                for (int r = 0; r < 4; r++) {
                    const int t = t0 + mr + g + ((r >= 2) ? 8 : 0);
                    const int f = nt*8 + 2*c + (r & 1);
                    if (t < T_ && f < HS_) {
                        const float rr = (r < 2) ? rlo : rhi;
                        g_atth[((size_t)(b*T_ + t))*E_ + h*HS_ + f] = __float2half(o[j][r] * rr);
                    }
                }
            }
        }
        named_bar(barid, 128);   // Pt/psum safe to reuse next tile
    }
}

// ---------------------------------------------------------------------------
extern "C" void kernel_launch(void* const* d_in, const int* in_sizes, int n_in,
                              void* d_out, int out_size)
{
    const float* x  = (const float*)d_in[0];
    const float* Wq = (const float*)d_in[1];
    const float* Wk = (const float*)d_in[2];
    const float* Wv = (const float*)d_in[3];
    const float* Wo = (const float*)d_in[4];
    const float* bo = (const float*)d_in[5];
    float* out = (float*)d_out;

    cudaFuncSetAttribute(gemm_f16<0>, cudaFuncAttributeMaxDynamicSharedMemorySize, GSMEM);
    cudaFuncSetAttribute(gemm_f16<1>, cudaFuncAttributeMaxDynamicSharedMemorySize, GSMEM);

    const int att_smem = ATT_WORDS * (int)sizeof(uint32_t);
    cudaFuncSetAttribute(attn_mma, cudaFuncAttributeMaxDynamicSharedMemorySize, att_smem);

    // prep: fp32 -> padded fp16
    cvt_x<<<(M_*(XP/2) + 255)/256, 256>>>(x);
    cvt_w<<<((1752+E_)*(XP/2) + 255)/256, 256>>>(Wq, Wk, Wv, Wo);

    // QKV projection (512 threads, 2 CTAs/SM -> 32 warps/SM)
    gemm_f16<0><<<dim3(14, 400), 512, GSMEM>>>(nullptr, nullptr);

    // attention (2 CTAs/SM)
    attn_mma<<<BH_, 512, att_smem>>>();

    // output projection
    gemm_f16<1><<<dim3(5, 400), 512, GSMEM>>>(bo, out);
}